// round 9
// baseline (speedup 1.0000x reference)
#include <cuda_runtime.h>

typedef unsigned long long ull;

#define NTOT 51840000   // 405*80*80*20

__device__ float g_mask1[6400];
__device__ float g_mask2[6400];

__global__ void mask_prep(const float* __restrict__ a1, const float* __restrict__ a2)
{
    int p = blockIdx.x * blockDim.x + threadIdx.x;
    if (p < 6400) {
        float s1 = 0.f, s2 = 0.f;
        const float* p1 = a1 + p * 20;
        const float* p2 = a2 + p * 20;
        #pragma unroll
        for (int z = 0; z < 20; ++z) { s1 += p1[z]; s2 += p2[z]; }
        g_mask1[p] = fminf(fmaxf(s1, 0.f), 1.f);
        g_mask2[p] = fminf(fmaxf(s2, 0.f), 1.f);
    }
}

__device__ __forceinline__ void unpack2(ull v, float& lo, float& hi) {
    asm("mov.b64 {%0, %1}, %2;" : "=f"(lo), "=f"(hi) : "l"(v));
}
__device__ __forceinline__ void fma2(ull& d, ull a, ull b) {
    asm("fma.rn.f32x2 %0, %1, %2, %0;" : "+l"(d) : "l"(a), "l"(b));
}
__device__ __forceinline__ ull shiftpair(ull a, ull b) {
    ull r;
    asm("{\n\t.reg .b32 alo, ahi, blo, bhi;\n\t"
        "mov.b64 {alo, ahi}, %1;\n\t"
        "mov.b64 {blo, bhi}, %2;\n\t"
        "mov.b64 %0, {ahi, blo};\n\t}"
        : "=l"(r) : "l"(a), "l"(b));
    return r;
}
__device__ __forceinline__ void cp16(unsigned dst, const void* src) {
    asm volatile("cp.async.cg.shared.global [%0], [%1], 16;" :: "r"(dst), "l"(src));
}
__device__ __forceinline__ void cp_commit() {
    asm volatile("cp.async.commit_group;" ::: "memory");
}
template<int N> __device__ __forceinline__ void cp_wait() {
    asm volatile("cp.async.wait_group %0;" :: "n"(N) : "memory");
}

// block: 240 threads, tid = zq + 5*x2c + 80*djg (zq fastest -> coalesced stores)
// grid : (x2b 6, y 80, di 9); dj = djg*3 + jl, x = x2g + 4 - dj
// 8 phases x 4 channels, double-buffered cp.async (R6 pipeline shape):
//  f1 buf: [c4][xl24][q5] quads (480 q = 7680 B each); xg = x2g0 + xl - 4, zero-pad
//  f2 buf: [c4][x2 16][13 quads] (832 q = 13312 B each); guard quads 0 & 6 = zero,
//          quads 1..5 = z 0..19 (unshifted)
// total smem = 2*7680 + 2*13312 = 41984 B -> 4 blocks/SM (reg-capped via launch_bounds)
#define F1B 7680
#define F2B 13312
#define F2BASE 15360
#define CADV 512000   // 4 channels * 128000 floats

__global__ void __launch_bounds__(240, 4) corr_kernel(
    const float* __restrict__ f1, const float* __restrict__ f2, float* __restrict__ out)
{
    extern __shared__ float smem[];
    const unsigned sb = (unsigned)__cvta_generic_to_shared(smem);

    const int x2b  = blockIdx.x;
    const int y    = blockIdx.y;
    const int di   = blockIdx.z;
    const int x2g0 = x2b * 16 - 4;
    const int y2   = y + di - 4;
    const bool yok = ((unsigned)y2 < 80u);
    const int tid  = threadIdx.x;

    const int zq  = tid % 5;
    const int x2c = (tid / 5) & 15;
    const int djg = tid / 80;
    const int x2g = x2g0 + x2c;

    // ---- precompute fill assignments (src offsets in floats; <0 = skip) ----
    int f1off[2]; unsigned f1dst[2];
    #pragma unroll
    for (int k = 0; k < 2; ++k) {
        int idx = tid + 240 * k;            // 0..479 quads
        int c  = idx / 120;
        int r  = idx - c * 120;
        int xl = r / 5;
        int q  = r - xl * 5;
        int xg = x2g0 + xl - 4;
        f1dst[k] = sb + idx * 16;
        f1off[k] = (yok && (unsigned)xg < 80u)
                   ? (c * 128000 + y * 1600 + xg * 20 + 4 * q) : (int)0x80000000;
    }
    int f2off[2]; unsigned f2dst[2];
    #pragma unroll
    for (int k = 0; k < 2; ++k) {
        int j = tid + 240 * k;              // 0..319 copies
        int i = j / 5;
        int m = j - i * 5;
        int c   = i >> 4;
        int x2l = i & 15;
        int x2  = x2g0 + x2l;
        f2dst[k] = sb + F2BASE + ((c * 16 + x2l) * 13 + 1 + m) * 16;
        f2off[k] = (j < 320 && yok && (unsigned)x2 < 80u)
                   ? (c * 128000 + y2 * 1600 + x2 * 20 + 4 * m) : (int)0x80000000;
    }

    // ---- zero both buffers (guards / OOB stay zero; cp.async writes valid only) ----
    {
        float4 z4 = make_float4(0.f, 0.f, 0.f, 0.f);
        for (int i = tid; i < 2624; i += 240) ((float4*)smem)[i] = z4;
    }
    __syncthreads();

    // ---- prologue: issue phase 0 into buffer 0 ----
    if (f1off[0] >= 0) cp16(f1dst[0], f1 + f1off[0]);
    if (f1off[1] >= 0) cp16(f1dst[1], f1 + f1off[1]);
    if (f2off[0] >= 0) cp16(f2dst[0], f2 + f2off[0]);
    if (f2off[1] >= 0) cp16(f2dst[1], f2 + f2off[1]);
    cp_commit();

    ull acc[30];
    #pragma unroll
    for (int i = 0; i < 30; ++i) acc[i] = 0ull;

    const int aq0 = (x2c + 8 - djg * 3) * 5 + zq;   // f1 quad idx (jl subtracts 5)
    const int bq0 = x2c * 13 + zq;                  // f2 quad idx within channel

    #pragma unroll 2
    for (int p = 0; p < 8; ++p) {
        const int cur = p & 1;
        // issue next phase into the other buffer
        if (p < 7) {
            const int adv = (p + 1) * CADV;
            const unsigned b1 = (1 - cur) * F1B, b2 = (1 - cur) * F2B;
            if (f1off[0] >= 0) cp16(f1dst[0] + b1, f1 + f1off[0] + adv);
            if (f1off[1] >= 0) cp16(f1dst[1] + b1, f1 + f1off[1] + adv);
            if (f2off[0] >= 0) cp16(f2dst[0] + b2, f2 + f2off[0] + adv);
            if (f2off[1] >= 0) cp16(f2dst[1] + b2, f2 + f2off[1] + adv);
            cp_commit();
            cp_wait<1>();
        } else {
            cp_wait<0>();
        }
        __syncthreads();

        if (yok) {
            const float* f1b = smem + cur * (F1B / 4);
            const float* f2b = smem + (F2BASE + cur * F2B) / 4;
            #pragma unroll
            for (int cl = 0; cl < 4; ++cl) {
                const float* bp = f2b + (cl * 208 + bq0) * 4;
                ull q0hi = *(const ull*)(bp + 2);                 // z 4zq-2,4zq-1
                ulonglong2 Q1 = *(const ulonglong2*)(bp + 4);     // z 4zq..4zq+3
                ull q2lo = *(const ull*)(bp + 8);                 // z 4zq+4,4zq+5
                ull P1 = shiftpair(q0hi, Q1.x);
                ull P3 = shiftpair(Q1.x, Q1.y);
                ull P5 = shiftpair(Q1.y, q2lo);
                #pragma unroll
                for (int jl = 0; jl < 3; ++jl) {
                    ulonglong2 av = *(const ulonglong2*)(f1b + (cl * 120 + aq0 - 5 * jl) * 4);
                    ull a01 = av.x, a23 = av.y;
                    ull* A = acc + jl * 10;
                    fma2(A[0], a01, q0hi); fma2(A[1], a23, Q1.x);   // dk=0
                    fma2(A[2], a01, P1  ); fma2(A[3], a23, P3  );   // dk=1
                    fma2(A[4], a01, Q1.x); fma2(A[5], a23, Q1.y);   // dk=2
                    fma2(A[6], a01, P3  ); fma2(A[7], a23, P5  );   // dk=3
                    fma2(A[8], a01, Q1.y); fma2(A[9], a23, q2lo);   // dk=4
                }
            }
        }
        __syncthreads();   // protect buf[cur] before next iteration's cp.async issue
    }

    // ---- epilogue: coalesced stores (z-fastest across lanes) ----
    {
        const bool x2ok = ((unsigned)x2g < 80u);
        const bool spin = yok && x2ok;
        const float m2v = spin ? g_mask2[y2 * 80 + x2g] : 1.f;
        const float inv = 1.f / 32.f;
        #pragma unroll
        for (int jl = 0; jl < 3; ++jl) {
            const int dj = djg * 3 + jl;
            const int x  = x2g + 4 - dj;
            if ((unsigned)x < 80u) {
                const float m1  = g_mask1[y * 80 + x];
                const float mIn = m1 * m2v;
                float* pc = out + (size_t)(di * 9 + dj) * 128000
                                + y * 1600 + x * 20 + 4 * zq;
                float* pm = pc + NTOT;
                #pragma unroll
                for (int dk = 0; dk < 5; ++dk) {
                    float4 cv;
                    unpack2(acc[jl * 10 + dk * 2 + 0], cv.x, cv.y);
                    unpack2(acc[jl * 10 + dk * 2 + 1], cv.z, cv.w);
                    cv.x *= inv; cv.y *= inv; cv.z *= inv; cv.w *= inv;
                    *(float4*)pc = cv;
                    float4 mv;
                    {
                        float* mp = (float*)&mv;
                        #pragma unroll
                        for (int zl = 0; zl < 4; ++zl) {
                            int z2 = 4 * zq + zl + dk - 2;
                            mp[zl] = (spin && (unsigned)z2 < 20u) ? mIn : m1;
                        }
                    }
                    *(float4*)pm = mv;
                    pc += (size_t)81 * 128000;
                    pm += (size_t)81 * 128000;
                }
            }
        }
    }
}

extern "C" void kernel_launch(void* const* d_in, const int* in_sizes, int n_in,
                              void* d_out, int out_size)
{
    (void)in_sizes; (void)n_in; (void)out_size;
    const float* f1 = (const float*)d_in[0];
    const float* a1 = (const float*)d_in[1];
    const float* f2 = (const float*)d_in[2];
    const float* a2 = (const float*)d_in[3];
    float* out = (float*)d_out;

    cudaFuncSetAttribute(corr_kernel, cudaFuncAttributeMaxDynamicSharedMemorySize, 41984);

    mask_prep<<<25, 256>>>(a1, a2);
    corr_kernel<<<dim3(6, 80, 9), 240, 41984>>>(f1, f2, out);
}

// round 10
// speedup vs baseline: 2.2811x; 2.2811x over previous
#include <cuda_runtime.h>

typedef unsigned long long ull;

#define NTOT 51840000   // 405*80*80*20

__device__ float g_mask1[6400];
__device__ float g_mask2[6400];

__global__ void mask_prep(const float* __restrict__ a1, const float* __restrict__ a2)
{
    int p = blockIdx.x * blockDim.x + threadIdx.x;
    if (p < 6400) {
        float s1 = 0.f, s2 = 0.f;
        const float* p1 = a1 + p * 20;
        const float* p2 = a2 + p * 20;
        #pragma unroll
        for (int z = 0; z < 20; ++z) { s1 += p1[z]; s2 += p2[z]; }
        g_mask1[p] = fminf(fmaxf(s1, 0.f), 1.f);
        g_mask2[p] = fminf(fmaxf(s2, 0.f), 1.f);
    }
}

__device__ __forceinline__ void unpack2(ull v, float& lo, float& hi) {
    asm("mov.b64 {%0, %1}, %2;" : "=f"(lo), "=f"(hi) : "l"(v));
}
__device__ __forceinline__ void fma2(ull& d, ull a, ull b) {
    asm("fma.rn.f32x2 %0, %1, %2, %0;" : "+l"(d) : "l"(a), "l"(b));
}
__device__ __forceinline__ ull shiftpair(ull a, ull b) {
    ull r;
    asm("{\n\t.reg .b32 alo, ahi, blo, bhi;\n\t"
        "mov.b64 {alo, ahi}, %1;\n\t"
        "mov.b64 {blo, bhi}, %2;\n\t"
        "mov.b64 %0, {ahi, blo};\n\t}"
        : "=l"(r) : "l"(a), "l"(b));
    return r;
}
__device__ __forceinline__ void cp16(unsigned dst, const void* src) {
    asm volatile("cp.async.cg.shared.global [%0], [%1], 16;" :: "r"(dst), "l"(src));
}
__device__ __forceinline__ void cp_commit() {
    asm volatile("cp.async.commit_group;" ::: "memory");
}
template<int N> __device__ __forceinline__ void cp_wait() {
    asm volatile("cp.async.wait_group %0;" :: "n"(N) : "memory");
}

// block: 240 threads, tid = zq + 5*x2c + 80*djg (zq fastest -> coalesced stores)
// grid : (x2b 6, y 80, di 9); dj = djg*3 + jl, x = x2g + 4 - dj
// 8 phases x 4 channels, double-buffered cp.async, depth-1 prefetch,
// ONE barrier per phase (wait -> barrier -> issue next -> compute).
//  f1 buf: [c4][xl24][q5] quads (480 q = 7680 B each); xg = x2g0 + xl - 4, zero-pad
//  f2 buf: [c4][x2 16][13 quads] (832 q = 13312 B each); guard quads 0 & 6 = zero,
//          quads 1..5 = z 0..19 (unshifted)
// smem = 2*7680 + 2*13312 = 41984 B -> 3 blocks/SM (reg-bound, 80 regs)
#define F1B 7680
#define F2B 13312
#define F2BASE 15360
#define CADV 512000   // 4 channels * 128000 floats

__global__ void __launch_bounds__(240, 3) corr_kernel(
    const float* __restrict__ f1, const float* __restrict__ f2, float* __restrict__ out)
{
    extern __shared__ float smem[];
    const unsigned sb = (unsigned)__cvta_generic_to_shared(smem);

    const int x2b  = blockIdx.x;
    const int y    = blockIdx.y;
    const int di   = blockIdx.z;
    const int x2g0 = x2b * 16 - 4;
    const int y2   = y + di - 4;
    const bool yok = ((unsigned)y2 < 80u);
    const int tid  = threadIdx.x;

    const int zq  = tid % 5;
    const int x2c = (tid / 5) & 15;
    const int djg = tid / 80;
    const int x2g = x2g0 + x2c;

    // ---- precompute fill assignments (src offsets in floats; <0 = skip) ----
    int f1off[2]; unsigned f1dst[2];
    #pragma unroll
    for (int k = 0; k < 2; ++k) {
        int idx = tid + 240 * k;            // 0..479 quads
        int c  = idx / 120;
        int r  = idx - c * 120;
        int xl = r / 5;
        int q  = r - xl * 5;
        int xg = x2g0 + xl - 4;
        f1dst[k] = sb + idx * 16;
        f1off[k] = (yok && (unsigned)xg < 80u)
                   ? (c * 128000 + y * 1600 + xg * 20 + 4 * q) : (int)0x80000000;
    }
    int f2off[2]; unsigned f2dst[2];
    #pragma unroll
    for (int k = 0; k < 2; ++k) {
        int j = tid + 240 * k;              // 0..319 copies
        int i = j / 5;
        int m = j - i * 5;
        int c   = i >> 4;
        int x2l = i & 15;
        int x2  = x2g0 + x2l;
        f2dst[k] = sb + F2BASE + ((c * 16 + x2l) * 13 + 1 + m) * 16;
        f2off[k] = (j < 320 && yok && (unsigned)x2 < 80u)
                   ? (c * 128000 + y2 * 1600 + x2 * 20 + 4 * m) : (int)0x80000000;
    }

    // ---- zero both buffers (guards / OOB stay zero; cp.async writes valid only) ----
    {
        float4 z4 = make_float4(0.f, 0.f, 0.f, 0.f);
        for (int i = tid; i < 2624; i += 240) ((float4*)smem)[i] = z4;
    }
    __syncthreads();

    // ---- prologue: issue phase 0 into buffer 0 ----
    if (f1off[0] >= 0) cp16(f1dst[0], f1 + f1off[0]);
    if (f1off[1] >= 0) cp16(f1dst[1], f1 + f1off[1]);
    if (f2off[0] >= 0) cp16(f2dst[0], f2 + f2off[0]);
    if (f2off[1] >= 0) cp16(f2dst[1], f2 + f2off[1]);
    cp_commit();

    ull acc[30];
    #pragma unroll
    for (int i = 0; i < 30; ++i) acc[i] = 0ull;

    const int aq0 = (x2c + 8 - djg * 3) * 5 + zq;   // f1 quad idx (jl subtracts 5)
    const int bq0 = x2c * 13 + zq;                  // f2 quad idx within channel

    #pragma unroll 2
    for (int p = 0; p < 8; ++p) {
        const int cur = p & 1;
        cp_wait<0>();          // phase-p data has arrived
        __syncthreads();       // visible to all; all finished compute(p-1) on buf[1-cur]
        // issue phase p+1 into buf[1-cur] (safe: barrier above) — overlaps compute(p)
        if (p < 7) {
            const int adv = (p + 1) * CADV;
            const unsigned b1 = (1 - cur) * F1B, b2 = (1 - cur) * F2B;
            if (f1off[0] >= 0) cp16(f1dst[0] + b1, f1 + f1off[0] + adv);
            if (f1off[1] >= 0) cp16(f1dst[1] + b1, f1 + f1off[1] + adv);
            if (f2off[0] >= 0) cp16(f2dst[0] + b2, f2 + f2off[0] + adv);
            if (f2off[1] >= 0) cp16(f2dst[1] + b2, f2 + f2off[1] + adv);
            cp_commit();
        }

        if (yok) {
            const float* f1b = smem + cur * (F1B / 4);
            const float* f2b = smem + (F2BASE + cur * F2B) / 4;
            #pragma unroll
            for (int cl = 0; cl < 4; ++cl) {
                const float* bp = f2b + (cl * 208 + bq0) * 4;
                ull q0hi = *(const ull*)(bp + 2);                 // z 4zq-2,4zq-1
                ulonglong2 Q1 = *(const ulonglong2*)(bp + 4);     // z 4zq..4zq+3
                ull q2lo = *(const ull*)(bp + 8);                 // z 4zq+4,4zq+5
                ull P1 = shiftpair(q0hi, Q1.x);
                ull P3 = shiftpair(Q1.x, Q1.y);
                ull P5 = shiftpair(Q1.y, q2lo);
                #pragma unroll
                for (int jl = 0; jl < 3; ++jl) {
                    ulonglong2 av = *(const ulonglong2*)(f1b + (cl * 120 + aq0 - 5 * jl) * 4);
                    ull a01 = av.x, a23 = av.y;
                    ull* A = acc + jl * 10;
                    fma2(A[0], a01, q0hi); fma2(A[1], a23, Q1.x);   // dk=0
                    fma2(A[2], a01, P1  ); fma2(A[3], a23, P3  );   // dk=1
                    fma2(A[4], a01, Q1.x); fma2(A[5], a23, Q1.y);   // dk=2
                    fma2(A[6], a01, P3  ); fma2(A[7], a23, P5  );   // dk=3
                    fma2(A[8], a01, Q1.y); fma2(A[9], a23, q2lo);   // dk=4
                }
            }
        }
    }

    // ---- epilogue: coalesced stores (z-fastest across lanes) ----
    // note: !spin => m2v = 1 => mIn == m1, so mask element = inrange ? mIn : m1
    {
        const bool x2ok = ((unsigned)x2g < 80u);
        const bool spin = yok && x2ok;
        const float m2v = spin ? g_mask2[y2 * 80 + x2g] : 1.f;
        const float inv = 1.f / 32.f;
        #pragma unroll
        for (int jl = 0; jl < 3; ++jl) {
            const int dj = djg * 3 + jl;
            const int x  = x2g + 4 - dj;
            if ((unsigned)x < 80u) {
                const float m1  = g_mask1[y * 80 + x];
                const float mIn = m1 * m2v;
                float* pc = out + (size_t)(di * 9 + dj) * 128000
                                + y * 1600 + x * 20 + 4 * zq;
                float* pm = pc + NTOT;
                #pragma unroll
                for (int dk = 0; dk < 5; ++dk) {
                    float4 cv;
                    unpack2(acc[jl * 10 + dk * 2 + 0], cv.x, cv.y);
                    unpack2(acc[jl * 10 + dk * 2 + 1], cv.z, cv.w);
                    cv.x *= inv; cv.y *= inv; cv.z *= inv; cv.w *= inv;
                    *(float4*)pc = cv;
                    float4 mv;
                    {
                        float* mp = (float*)&mv;
                        #pragma unroll
                        for (int zl = 0; zl < 4; ++zl) {
                            int z2 = 4 * zq + zl + dk - 2;
                            mp[zl] = ((unsigned)z2 < 20u) ? mIn : m1;
                        }
                    }
                    *(float4*)pm = mv;
                    pc += (size_t)81 * 128000;
                    pm += (size_t)81 * 128000;
                }
            }
        }
    }
}

extern "C" void kernel_launch(void* const* d_in, const int* in_sizes, int n_in,
                              void* d_out, int out_size)
{
    (void)in_sizes; (void)n_in; (void)out_size;
    const float* f1 = (const float*)d_in[0];
    const float* a1 = (const float*)d_in[1];
    const float* f2 = (const float*)d_in[2];
    const float* a2 = (const float*)d_in[3];
    float* out = (float*)d_out;

    cudaFuncSetAttribute(corr_kernel, cudaFuncAttributeMaxDynamicSharedMemorySize, 41984);

    mask_prep<<<25, 256>>>(a1, a2);
    corr_kernel<<<dim3(6, 80, 9), 240, 41984>>>(f1, f2, out);
}

// round 11
// speedup vs baseline: 3.5420x; 1.5528x over previous
#include <cuda_runtime.h>

typedef unsigned long long ull;

#define NTOT 51840000   // 405*80*80*20

__device__ float g_mask1[6400];
__device__ float g_mask2[6400];

__global__ void mask_prep(const float* __restrict__ a1, const float* __restrict__ a2)
{
    int p = blockIdx.x * blockDim.x + threadIdx.x;
    if (p < 6400) {
        float s1 = 0.f, s2 = 0.f;
        const float* p1 = a1 + p * 20;
        const float* p2 = a2 + p * 20;
        #pragma unroll
        for (int z = 0; z < 20; ++z) { s1 += p1[z]; s2 += p2[z]; }
        g_mask1[p] = fminf(fmaxf(s1, 0.f), 1.f);
        g_mask2[p] = fminf(fmaxf(s2, 0.f), 1.f);
    }
}

__device__ __forceinline__ void unpack2(ull v, float& lo, float& hi) {
    asm("mov.b64 {%0, %1}, %2;" : "=f"(lo), "=f"(hi) : "l"(v));
}
__device__ __forceinline__ void fma2(ull& d, ull a, ull b) {
    asm("fma.rn.f32x2 %0, %1, %2, %0;" : "+l"(d) : "l"(a), "l"(b));
}
__device__ __forceinline__ ull shiftpair(ull a, ull b) {
    ull r;
    asm("{\n\t.reg .b32 alo, ahi, blo, bhi;\n\t"
        "mov.b64 {alo, ahi}, %1;\n\t"
        "mov.b64 {blo, bhi}, %2;\n\t"
        "mov.b64 %0, {ahi, blo};\n\t}"
        : "=l"(r) : "l"(a), "l"(b));
    return r;
}
__device__ __forceinline__ void cp16(unsigned dst, const void* src) {
    asm volatile("cp.async.cg.shared.global [%0], [%1], 16;" :: "r"(dst), "l"(src));
}
__device__ __forceinline__ void cp_commit() {
    asm volatile("cp.async.commit_group;" ::: "memory");
}
template<int N> __device__ __forceinline__ void cp_wait() {
    asm volatile("cp.async.wait_group %0;" :: "n"(N) : "memory");
}

// operand register set for one channel (20 regs)
struct Ops {
    ull a01_0, a23_0, a01_1, a23_1, a01_2, a23_2;   // a pairs for jl=0,1,2
    ull q0hi;         // z 4zq-2..4zq-1
    ulonglong2 Q1;    // z 4zq..4zq+3
    ull q2lo;         // z 4zq+4..4zq+5
};

__device__ __forceinline__ void load_ops(Ops& o, const float* f1b, const float* f2b,
                                         int cl, int aq0, int bq0)
{
    const float* bp = f2b + (cl * 208 + bq0) * 4;
    o.q0hi = *(const ull*)(bp + 2);
    o.Q1   = *(const ulonglong2*)(bp + 4);
    o.q2lo = *(const ull*)(bp + 8);
    ulonglong2 av;
    av = *(const ulonglong2*)(f1b + (cl * 120 + aq0     ) * 4); o.a01_0 = av.x; o.a23_0 = av.y;
    av = *(const ulonglong2*)(f1b + (cl * 120 + aq0 -  5) * 4); o.a01_1 = av.x; o.a23_1 = av.y;
    av = *(const ulonglong2*)(f1b + (cl * 120 + aq0 - 10) * 4); o.a01_2 = av.x; o.a23_2 = av.y;
}

__device__ __forceinline__ void compute_ops(ull* acc, const Ops& o)
{
    ull P1 = shiftpair(o.q0hi, o.Q1.x);
    ull P3 = shiftpair(o.Q1.x, o.Q1.y);
    ull P5 = shiftpair(o.Q1.y, o.q2lo);
    #pragma unroll
    for (int jl = 0; jl < 3; ++jl) {
        ull a01 = (jl == 0) ? o.a01_0 : (jl == 1) ? o.a01_1 : o.a01_2;
        ull a23 = (jl == 0) ? o.a23_0 : (jl == 1) ? o.a23_1 : o.a23_2;
        ull* A = acc + jl * 10;
        fma2(A[0], a01, o.q0hi); fma2(A[1], a23, o.Q1.x);   // dk=0
        fma2(A[2], a01, P1    ); fma2(A[3], a23, P3    );   // dk=1
        fma2(A[4], a01, o.Q1.x); fma2(A[5], a23, o.Q1.y);   // dk=2
        fma2(A[6], a01, P3    ); fma2(A[7], a23, P5    );   // dk=3
        fma2(A[8], a01, o.Q1.y); fma2(A[9], a23, o.q2lo);   // dk=4
    }
}

// block: 240 threads, tid = zq + 5*x2c + 80*djg (zq fastest -> coalesced stores)
// grid : (x2b 6, y 80, di 9); dj = djg*3 + jl, x = x2g + 4 - dj
// 8 phases x 4 channels, double-buffered cp.async (depth-1 prefetch) +
// register double-buffered operands (2 blocks/SM, ~115 regs).
//  f1 buf: [c4][xl24][q5] quads (480 q = 7680 B each); xg = x2g0 + xl - 4, zero-pad
//  f2 buf: [c4][x2 16][13 quads] (832 q = 13312 B each); guard quads 0 & 6 = zero,
//          quads 1..5 = z 0..19 (unshifted)
// smem = 41984 B
#define F1B 7680
#define F2B 13312
#define F2BASE 15360
#define CADV 512000   // 4 channels * 128000 floats

__global__ void __launch_bounds__(240, 2) corr_kernel(
    const float* __restrict__ f1, const float* __restrict__ f2, float* __restrict__ out)
{
    extern __shared__ float smem[];
    const unsigned sb = (unsigned)__cvta_generic_to_shared(smem);

    const int x2b  = blockIdx.x;
    const int y    = blockIdx.y;
    const int di   = blockIdx.z;
    const int x2g0 = x2b * 16 - 4;
    const int y2   = y + di - 4;
    const bool yok = ((unsigned)y2 < 80u);
    const int tid  = threadIdx.x;

    const int zq  = tid % 5;
    const int x2c = (tid / 5) & 15;
    const int djg = tid / 80;
    const int x2g = x2g0 + x2c;

    // ---- precompute fill assignments (src offsets in floats; <0 = skip) ----
    int f1off[2]; unsigned f1dst[2];
    #pragma unroll
    for (int k = 0; k < 2; ++k) {
        int idx = tid + 240 * k;            // 0..479 quads
        int c  = idx / 120;
        int r  = idx - c * 120;
        int xl = r / 5;
        int q  = r - xl * 5;
        int xg = x2g0 + xl - 4;
        f1dst[k] = sb + idx * 16;
        f1off[k] = (yok && (unsigned)xg < 80u)
                   ? (c * 128000 + y * 1600 + xg * 20 + 4 * q) : (int)0x80000000;
    }
    int f2off[2]; unsigned f2dst[2];
    #pragma unroll
    for (int k = 0; k < 2; ++k) {
        int j = tid + 240 * k;              // 0..319 copies
        int i = j / 5;
        int m = j - i * 5;
        int c   = i >> 4;
        int x2l = i & 15;
        int x2  = x2g0 + x2l;
        f2dst[k] = sb + F2BASE + ((c * 16 + x2l) * 13 + 1 + m) * 16;
        f2off[k] = (j < 320 && yok && (unsigned)x2 < 80u)
                   ? (c * 128000 + y2 * 1600 + x2 * 20 + 4 * m) : (int)0x80000000;
    }

    // ---- zero both buffers (guards / OOB stay zero; cp.async writes valid only) ----
    {
        float4 z4 = make_float4(0.f, 0.f, 0.f, 0.f);
        for (int i = tid; i < 2624; i += 240) ((float4*)smem)[i] = z4;
    }
    __syncthreads();

    // ---- prologue: issue phase 0 into buffer 0 ----
    if (f1off[0] >= 0) cp16(f1dst[0], f1 + f1off[0]);
    if (f1off[1] >= 0) cp16(f1dst[1], f1 + f1off[1]);
    if (f2off[0] >= 0) cp16(f2dst[0], f2 + f2off[0]);
    if (f2off[1] >= 0) cp16(f2dst[1], f2 + f2off[1]);
    cp_commit();

    ull acc[30];
    #pragma unroll
    for (int i = 0; i < 30; ++i) acc[i] = 0ull;

    const int aq0 = (x2c + 8 - djg * 3) * 5 + zq;   // f1 quad idx (jl subtracts 5)
    const int bq0 = x2c * 13 + zq;                  // f2 quad idx within channel

    #pragma unroll 2
    for (int p = 0; p < 8; ++p) {
        const int cur = p & 1;
        cp_wait<0>();          // phase-p data has arrived
        __syncthreads();       // visible to all; all finished compute(p-1) on buf[1-cur]
        // issue phase p+1 into buf[1-cur] (safe: barrier above) — overlaps compute(p)
        if (p < 7) {
            const int adv = (p + 1) * CADV;
            const unsigned b1 = (1 - cur) * F1B, b2 = (1 - cur) * F2B;
            if (f1off[0] >= 0) cp16(f1dst[0] + b1, f1 + f1off[0] + adv);
            if (f1off[1] >= 0) cp16(f1dst[1] + b1, f1 + f1off[1] + adv);
            if (f2off[0] >= 0) cp16(f2dst[0] + b2, f2 + f2off[0] + adv);
            if (f2off[1] >= 0) cp16(f2dst[1] + b2, f2 + f2off[1] + adv);
            cp_commit();
        }

        if (yok) {
            const float* f1b = smem + cur * (F1B / 4);
            const float* f2b = smem + (F2BASE + cur * F2B) / 4;
            // register-pipelined over the 4 channels of this phase
            Ops b0, b1;
            load_ops(b0, f1b, f2b, 0, aq0, bq0);
            load_ops(b1, f1b, f2b, 1, aq0, bq0);
            compute_ops(acc, b0);
            load_ops(b0, f1b, f2b, 2, aq0, bq0);
            compute_ops(acc, b1);
            load_ops(b1, f1b, f2b, 3, aq0, bq0);
            compute_ops(acc, b0);
            compute_ops(acc, b1);
        }
    }

    // ---- epilogue: coalesced stores (z-fastest across lanes) ----
    // note: !spin => m2v = 1 => mIn == m1, so mask element = inrange ? mIn : m1
    {
        const bool x2ok = ((unsigned)x2g < 80u);
        const bool spin = yok && x2ok;
        const float m2v = spin ? g_mask2[y2 * 80 + x2g] : 1.f;
        const float inv = 1.f / 32.f;
        #pragma unroll
        for (int jl = 0; jl < 3; ++jl) {
            const int dj = djg * 3 + jl;
            const int x  = x2g + 4 - dj;
            if ((unsigned)x < 80u) {
                const float m1  = g_mask1[y * 80 + x];
                const float mIn = m1 * m2v;
                float* pc = out + (size_t)(di * 9 + dj) * 128000
                                + y * 1600 + x * 20 + 4 * zq;
                float* pm = pc + NTOT;
                #pragma unroll
                for (int dk = 0; dk < 5; ++dk) {
                    float4 cv;
                    unpack2(acc[jl * 10 + dk * 2 + 0], cv.x, cv.y);
                    unpack2(acc[jl * 10 + dk * 2 + 1], cv.z, cv.w);
                    cv.x *= inv; cv.y *= inv; cv.z *= inv; cv.w *= inv;
                    *(float4*)pc = cv;
                    float4 mv;
                    {
                        float* mp = (float*)&mv;
                        #pragma unroll
                        for (int zl = 0; zl < 4; ++zl) {
                            int z2 = 4 * zq + zl + dk - 2;
                            mp[zl] = ((unsigned)z2 < 20u) ? mIn : m1;
                        }
                    }
                    *(float4*)pm = mv;
                    pc += (size_t)81 * 128000;
                    pm += (size_t)81 * 128000;
                }
            }
        }
    }
}

extern "C" void kernel_launch(void* const* d_in, const int* in_sizes, int n_in,
                              void* d_out, int out_size)
{
    (void)in_sizes; (void)n_in; (void)out_size;
    const float* f1 = (const float*)d_in[0];
    const float* a1 = (const float*)d_in[1];
    const float* f2 = (const float*)d_in[2];
    const float* a2 = (const float*)d_in[3];
    float* out = (float*)d_out;

    cudaFuncSetAttribute(corr_kernel, cudaFuncAttributeMaxDynamicSharedMemorySize, 41984);

    mask_prep<<<25, 256>>>(a1, a2);
    corr_kernel<<<dim3(6, 80, 9), 240, 41984>>>(f1, f2, out);
}

// round 12
// speedup vs baseline: 3.8309x; 1.0816x over previous
#include <cuda_runtime.h>

typedef unsigned long long ull;

#define NTOT 51840000   // 405*80*80*20

__device__ float g_mask1[6400];
__device__ float g_mask2[6400];

__global__ void mask_prep(const float* __restrict__ a1, const float* __restrict__ a2)
{
    int p = blockIdx.x * blockDim.x + threadIdx.x;
    if (p < 6400) {
        float s1 = 0.f, s2 = 0.f;
        const float* p1 = a1 + p * 20;
        const float* p2 = a2 + p * 20;
        #pragma unroll
        for (int z = 0; z < 20; ++z) { s1 += p1[z]; s2 += p2[z]; }
        g_mask1[p] = fminf(fmaxf(s1, 0.f), 1.f);
        g_mask2[p] = fminf(fmaxf(s2, 0.f), 1.f);
    }
}

__device__ __forceinline__ void unpack2(ull v, float& lo, float& hi) {
    asm("mov.b64 {%0, %1}, %2;" : "=f"(lo), "=f"(hi) : "l"(v));
}
__device__ __forceinline__ void fma2(ull& d, ull a, ull b) {
    asm("fma.rn.f32x2 %0, %1, %2, %0;" : "+l"(d) : "l"(a), "l"(b));
}
__device__ __forceinline__ ull shiftpair(ull a, ull b) {
    ull r;
    asm("{\n\t.reg .b32 alo, ahi, blo, bhi;\n\t"
        "mov.b64 {alo, ahi}, %1;\n\t"
        "mov.b64 {blo, bhi}, %2;\n\t"
        "mov.b64 %0, {ahi, blo};\n\t}"
        : "=l"(r) : "l"(a), "l"(b));
    return r;
}
__device__ __forceinline__ void cp16(unsigned dst, const void* src) {
    asm volatile("cp.async.cg.shared.global [%0], [%1], 16;" :: "r"(dst), "l"(src));
}
__device__ __forceinline__ void cp_commit() {
    asm volatile("cp.async.commit_group;" ::: "memory");
}
template<int N> __device__ __forceinline__ void cp_wait() {
    asm volatile("cp.async.wait_group %0;" :: "n"(N) : "memory");
}

// operand register set for one channel (20 regs)
struct Ops {
    ull a01_0, a23_0, a01_1, a23_1, a01_2, a23_2;   // a pairs for jl=0,1,2
    ull q0hi;         // z 4zq-2..4zq-1
    ulonglong2 Q1;    // z 4zq..4zq+3
    ull q2lo;         // z 4zq+4..4zq+5
};

__device__ __forceinline__ void load_ops(Ops& o, const float* f1b, const float* f2b,
                                         int cl, int aq0, int bq0)
{
    const float* bp = f2b + (cl * 208 + bq0) * 4;
    o.q0hi = *(const ull*)(bp + 2);
    o.Q1   = *(const ulonglong2*)(bp + 4);
    o.q2lo = *(const ull*)(bp + 8);
    ulonglong2 av;
    av = *(const ulonglong2*)(f1b + (cl * 120 + aq0     ) * 4); o.a01_0 = av.x; o.a23_0 = av.y;
    av = *(const ulonglong2*)(f1b + (cl * 120 + aq0 -  5) * 4); o.a01_1 = av.x; o.a23_1 = av.y;
    av = *(const ulonglong2*)(f1b + (cl * 120 + aq0 - 10) * 4); o.a01_2 = av.x; o.a23_2 = av.y;
}

__device__ __forceinline__ void compute_ops(ull* acc, const Ops& o)
{
    ull P1 = shiftpair(o.q0hi, o.Q1.x);
    ull P3 = shiftpair(o.Q1.x, o.Q1.y);
    ull P5 = shiftpair(o.Q1.y, o.q2lo);
    #pragma unroll
    for (int jl = 0; jl < 3; ++jl) {
        ull a01 = (jl == 0) ? o.a01_0 : (jl == 1) ? o.a01_1 : o.a01_2;
        ull a23 = (jl == 0) ? o.a23_0 : (jl == 1) ? o.a23_1 : o.a23_2;
        ull* A = acc + jl * 10;
        fma2(A[0], a01, o.q0hi); fma2(A[1], a23, o.Q1.x);   // dk=0
        fma2(A[2], a01, P1    ); fma2(A[3], a23, P3    );   // dk=1
        fma2(A[4], a01, o.Q1.x); fma2(A[5], a23, o.Q1.y);   // dk=2
        fma2(A[6], a01, P3    ); fma2(A[7], a23, P5    );   // dk=3
        fma2(A[8], a01, o.Q1.y); fma2(A[9], a23, o.q2lo);   // dk=4
    }
}

// block: 240 threads, tid = zq + 5*x2c + 80*djg (zq fastest -> coalesced stores)
// grid : (x2b 6, y 80, di 9); dj = djg*3 + jl, x = x2g + 4 - dj
// 4 phases x 8 channels, double-buffered cp.async (depth-1 prefetch) +
// register double-buffered operands (2 blocks/SM).
//  f1 buf: [c8][xl24][q5] quads (960 q = 15360 B each); xg = x2g0 + xl - 4, zero-pad
//  f2 buf: [c8][x2 16][13 quads] (1664 q = 26624 B each); guard quads 0 & 6 = zero,
//          quads 1..5 = z 0..19 (unshifted)
// smem = 2*15360 + 2*26624 = 83968 B -> 2 blocks/SM
#define F1B 15360
#define F2B 26624
#define F2BASE 30720          // bytes
#define F2BASEQ 1920          // quads
#define CADV 1024000          // 8 channels * 128000 floats

__global__ void __launch_bounds__(240, 2) corr_kernel(
    const float* __restrict__ f1, const float* __restrict__ f2, float* __restrict__ out)
{
    extern __shared__ float smem[];
    const unsigned sb = (unsigned)__cvta_generic_to_shared(smem);

    const int x2b  = blockIdx.x;
    const int y    = blockIdx.y;
    const int di   = blockIdx.z;
    const int x2g0 = x2b * 16 - 4;
    const int y2   = y + di - 4;
    const bool yok = ((unsigned)y2 < 80u);
    const int tid  = threadIdx.x;

    const int zq  = tid % 5;
    const int x2c = (tid / 5) & 15;
    const int djg = tid / 80;
    const int x2g = x2g0 + x2c;

    // ---- precompute fill assignments (src offsets in floats; <0 = skip) ----
    int f1off[4]; unsigned f1dst[4];
    #pragma unroll
    for (int k = 0; k < 4; ++k) {
        int idx = tid + 240 * k;            // 0..959 quads
        int c  = idx / 120;
        int r  = idx - c * 120;
        int xl = r / 5;
        int q  = r - xl * 5;
        int xg = x2g0 + xl - 4;
        f1dst[k] = sb + idx * 16;
        f1off[k] = (yok && (unsigned)xg < 80u)
                   ? (c * 128000 + y * 1600 + xg * 20 + 4 * q) : (int)0x80000000;
    }
    int f2off[3]; unsigned f2dst[3];
    #pragma unroll
    for (int k = 0; k < 3; ++k) {
        int j = tid + 240 * k;              // 0..639 copies
        int i = j / 5;
        int m = j - i * 5;
        int c   = i >> 4;
        int x2l = i & 15;
        int x2  = x2g0 + x2l;
        f2dst[k] = sb + F2BASE + ((c * 16 + x2l) * 13 + 1 + m) * 16;
        f2off[k] = (j < 640 && yok && (unsigned)x2 < 80u)
                   ? (c * 128000 + y2 * 1600 + x2 * 20 + 4 * m) : (int)0x80000000;
    }

    // ---- zeroing: interior blocks only need f2 guard quads; edge blocks all ----
    if (yok) {
        float4 z4 = make_float4(0.f, 0.f, 0.f, 0.f);
        if (x2b == 0 || x2b == 5) {
            for (int i = tid; i < 5248; i += 240) ((float4*)smem)[i] = z4;
        } else {
            // 512 guard quads: 2 buffers x 8 c x 16 x2l x {quad 0, quad 6}
            for (int i = tid; i < 512; i += 240) {
                int e   = i & 255;
                int cx  = e >> 1;                  // c*16 + x2l  (0..127)
                int g   = (e & 1) * 6;
                int quad = F2BASEQ + (i >> 8) * (F2B / 16) + cx * 13 + g;
                ((float4*)smem)[quad] = z4;
            }
        }
    }
    __syncthreads();

    // ---- prologue: issue phase 0 into buffer 0 ----
    if (f1off[0] >= 0) cp16(f1dst[0], f1 + f1off[0]);
    if (f1off[1] >= 0) cp16(f1dst[1], f1 + f1off[1]);
    if (f1off[2] >= 0) cp16(f1dst[2], f1 + f1off[2]);
    if (f1off[3] >= 0) cp16(f1dst[3], f1 + f1off[3]);
    if (f2off[0] >= 0) cp16(f2dst[0], f2 + f2off[0]);
    if (f2off[1] >= 0) cp16(f2dst[1], f2 + f2off[1]);
    if (f2off[2] >= 0) cp16(f2dst[2], f2 + f2off[2]);
    cp_commit();

    ull acc[30];
    #pragma unroll
    for (int i = 0; i < 30; ++i) acc[i] = 0ull;

    const int aq0 = (x2c + 8 - djg * 3) * 5 + zq;   // f1 quad idx (jl subtracts 5)
    const int bq0 = x2c * 13 + zq;                  // f2 quad idx within channel

    #pragma unroll 2
    for (int p = 0; p < 4; ++p) {
        const int cur = p & 1;
        cp_wait<0>();          // phase-p data has arrived
        __syncthreads();       // visible to all; all finished compute(p-1) on buf[1-cur]
        // issue phase p+1 into buf[1-cur] (safe: barrier above) — overlaps compute(p)
        if (p < 3) {
            const int adv = (p + 1) * CADV;
            const unsigned b1 = (1 - cur) * F1B, b2 = (1 - cur) * F2B;
            if (f1off[0] >= 0) cp16(f1dst[0] + b1, f1 + f1off[0] + adv);
            if (f1off[1] >= 0) cp16(f1dst[1] + b1, f1 + f1off[1] + adv);
            if (f1off[2] >= 0) cp16(f1dst[2] + b1, f1 + f1off[2] + adv);
            if (f1off[3] >= 0) cp16(f1dst[3] + b1, f1 + f1off[3] + adv);
            if (f2off[0] >= 0) cp16(f2dst[0] + b2, f2 + f2off[0] + adv);
            if (f2off[1] >= 0) cp16(f2dst[1] + b2, f2 + f2off[1] + adv);
            if (f2off[2] >= 0) cp16(f2dst[2] + b2, f2 + f2off[2] + adv);
            cp_commit();
        }

        if (yok) {
            const float* f1b = smem + cur * (F1B / 4);
            const float* f2b = smem + (F2BASE + cur * F2B) / 4;
            // register-pipelined over the 8 channels of this phase
            Ops b0, b1;
            load_ops(b0, f1b, f2b, 0, aq0, bq0);
            load_ops(b1, f1b, f2b, 1, aq0, bq0);
            #pragma unroll
            for (int cl = 0; cl < 6; cl += 2) {
                compute_ops(acc, b0); load_ops(b0, f1b, f2b, cl + 2, aq0, bq0);
                compute_ops(acc, b1); load_ops(b1, f1b, f2b, cl + 3, aq0, bq0);
            }
            compute_ops(acc, b0);
            compute_ops(acc, b1);
        }
    }

    // ---- epilogue: coalesced stores (z-fastest across lanes) ----
    // note: !spin => m2v = 1 => mIn == m1, so mask element = inrange ? mIn : m1
    {
        const bool x2ok = ((unsigned)x2g < 80u);
        const bool spin = yok && x2ok;
        const float m2v = spin ? g_mask2[y2 * 80 + x2g] : 1.f;
        const float inv = 1.f / 32.f;
        #pragma unroll
        for (int jl = 0; jl < 3; ++jl) {
            const int dj = djg * 3 + jl;
            const int x  = x2g + 4 - dj;
            if ((unsigned)x < 80u) {
                const float m1  = g_mask1[y * 80 + x];
                const float mIn = m1 * m2v;
                float* pc = out + (size_t)(di * 9 + dj) * 128000
                                + y * 1600 + x * 20 + 4 * zq;
                float* pm = pc + NTOT;
                #pragma unroll
                for (int dk = 0; dk < 5; ++dk) {
                    float4 cv;
                    unpack2(acc[jl * 10 + dk * 2 + 0], cv.x, cv.y);
                    unpack2(acc[jl * 10 + dk * 2 + 1], cv.z, cv.w);
                    cv.x *= inv; cv.y *= inv; cv.z *= inv; cv.w *= inv;
                    *(float4*)pc = cv;
                    float4 mv;
                    {
                        float* mp = (float*)&mv;
                        #pragma unroll
                        for (int zl = 0; zl < 4; ++zl) {
                            int z2 = 4 * zq + zl + dk - 2;
                            mp[zl] = ((unsigned)z2 < 20u) ? mIn : m1;
                        }
                    }
                    *(float4*)pm = mv;
                    pc += (size_t)81 * 128000;
                    pm += (size_t)81 * 128000;
                }
            }
        }
    }
}

extern "C" void kernel_launch(void* const* d_in, const int* in_sizes, int n_in,
                              void* d_out, int out_size)
{
    (void)in_sizes; (void)n_in; (void)out_size;
    const float* f1 = (const float*)d_in[0];
    const float* a1 = (const float*)d_in[1];
    const float* f2 = (const float*)d_in[2];
    const float* a2 = (const float*)d_in[3];
    float* out = (float*)d_out;

    cudaFuncSetAttribute(corr_kernel, cudaFuncAttributeMaxDynamicSharedMemorySize, 83968);

    mask_prep<<<25, 256>>>(a1, a2);
    corr_kernel<<<dim3(6, 80, 9), 240, 83968>>>(f1, f2, out);
}

// round 13
// speedup vs baseline: 3.8821x; 1.0134x over previous
#include <cuda_runtime.h>

typedef unsigned long long ull;

#define NTOT 51840000   // 405*80*80*20

__device__ float g_mask1[6400];
__device__ float g_mask2[6400];

__global__ void mask_prep(const float* __restrict__ a1, const float* __restrict__ a2)
{
    int p = blockIdx.x * blockDim.x + threadIdx.x;
    if (p < 6400) {
        float s1 = 0.f, s2 = 0.f;
        const float* p1 = a1 + p * 20;
        const float* p2 = a2 + p * 20;
        #pragma unroll
        for (int z = 0; z < 20; ++z) { s1 += p1[z]; s2 += p2[z]; }
        g_mask1[p] = fminf(fmaxf(s1, 0.f), 1.f);
        g_mask2[p] = fminf(fmaxf(s2, 0.f), 1.f);
    }
}

__device__ __forceinline__ void unpack2(ull v, float& lo, float& hi) {
    asm("mov.b64 {%0, %1}, %2;" : "=f"(lo), "=f"(hi) : "l"(v));
}
__device__ __forceinline__ void fma2(ull& d, ull a, ull b) {
    asm("fma.rn.f32x2 %0, %1, %2, %0;" : "+l"(d) : "l"(a), "l"(b));
}
__device__ __forceinline__ ull shiftpair(ull a, ull b) {
    ull r;
    asm("{\n\t.reg .b32 alo, ahi, blo, bhi;\n\t"
        "mov.b64 {alo, ahi}, %1;\n\t"
        "mov.b64 {blo, bhi}, %2;\n\t"
        "mov.b64 %0, {ahi, blo};\n\t}"
        : "=l"(r) : "l"(a), "l"(b));
    return r;
}
__device__ __forceinline__ void cp16(unsigned dst, const void* src) {
    asm volatile("cp.async.cg.shared.global [%0], [%1], 16;" :: "r"(dst), "l"(src));
}
__device__ __forceinline__ void cp_commit() {
    asm volatile("cp.async.commit_group;" ::: "memory");
}
template<int N> __device__ __forceinline__ void cp_wait() {
    asm volatile("cp.async.wait_group %0;" :: "n"(N) : "memory");
}

// b-window for one channel (8 regs)
struct BW {
    ull q0hi;         // z 4zq-2..4zq-1
    ulonglong2 Q1;    // z 4zq..4zq+3
    ull q2lo;         // z 4zq+4..4zq+5
};

__device__ __forceinline__ void loadB(BW& b, const float* f2b, int cl, int bq0)
{
    const float* bp = f2b + (cl * 208 + bq0) * 4;
    b.q0hi = *(const ull*)(bp + 2);
    b.Q1   = *(const ulonglong2*)(bp + 4);
    b.q2lo = *(const ull*)(bp + 8);
}
__device__ __forceinline__ ulonglong2 loadA(const float* f1b, int cl, int aq)
{
    return *(const ulonglong2*)(f1b + (cl * 120 + aq) * 4);
}

// 10 fma2 for one (channel, jl): 5 dk x 2 z-pairs
__device__ __forceinline__ void fma10(ull* A, ulonglong2 a, const BW& b,
                                      ull P1, ull P3, ull P5)
{
    fma2(A[0], a.x, b.q0hi); fma2(A[1], a.y, b.Q1.x);   // dk=0
    fma2(A[2], a.x, P1    ); fma2(A[3], a.y, P3    );   // dk=1
    fma2(A[4], a.x, b.Q1.x); fma2(A[5], a.y, b.Q1.y);   // dk=2
    fma2(A[6], a.x, P3    ); fma2(A[7], a.y, P5    );   // dk=3
    fma2(A[8], a.x, b.Q1.y); fma2(A[9], a.y, b.q2lo);   // dk=4
}

// block: 240 threads, tid = zq + 5*x2c + 80*djg (zq fastest -> coalesced stores)
// grid : (x2b 6, y 80, di 9); dj = djg*3 + jl, x = x2g + 4 - dj
// 4 phases x 8 channels, double-buffered cp.async (depth-1 prefetch);
// operand pipeline: b-window ping-pong (distance 1 channel) + 3-slot JIT a-pairs.
//  f1 buf: [c8][xl24][q5] quads (960 q = 15360 B each); xg = x2g0 + xl - 4, zero-pad
//  f2 buf: [c8][x2 16][13 quads] (1664 q = 26624 B each); guard quads 0 & 6 = zero,
//          quads 1..5 = z 0..19 (unshifted)
// smem = 2*15360 + 2*26624 = 83968 B -> 2 blocks/SM
#define F1B 15360
#define F2B 26624
#define F2BASE 30720          // bytes
#define F2BASEQ 1920          // quads
#define CADV 1024000          // 8 channels * 128000 floats

__global__ void __launch_bounds__(240, 2) corr_kernel(
    const float* __restrict__ f1, const float* __restrict__ f2, float* __restrict__ out)
{
    extern __shared__ float smem[];
    const unsigned sb = (unsigned)__cvta_generic_to_shared(smem);

    const int x2b  = blockIdx.x;
    const int y    = blockIdx.y;
    const int di   = blockIdx.z;
    const int x2g0 = x2b * 16 - 4;
    const int y2   = y + di - 4;
    const bool yok = ((unsigned)y2 < 80u);
    const int tid  = threadIdx.x;

    const int zq  = tid % 5;
    const int x2c = (tid / 5) & 15;
    const int djg = tid / 80;
    const int x2g = x2g0 + x2c;

    // ---- precompute fill assignments (src offsets in floats; <0 = skip) ----
    int f1off[4]; unsigned f1dst[4];
    #pragma unroll
    for (int k = 0; k < 4; ++k) {
        int idx = tid + 240 * k;            // 0..959 quads
        int c  = idx / 120;
        int r  = idx - c * 120;
        int xl = r / 5;
        int q  = r - xl * 5;
        int xg = x2g0 + xl - 4;
        f1dst[k] = sb + idx * 16;
        f1off[k] = (yok && (unsigned)xg < 80u)
                   ? (c * 128000 + y * 1600 + xg * 20 + 4 * q) : (int)0x80000000;
    }
    int f2off[3]; unsigned f2dst[3];
    #pragma unroll
    for (int k = 0; k < 3; ++k) {
        int j = tid + 240 * k;              // 0..639 copies
        int i = j / 5;
        int m = j - i * 5;
        int c   = i >> 4;
        int x2l = i & 15;
        int x2  = x2g0 + x2l;
        f2dst[k] = sb + F2BASE + ((c * 16 + x2l) * 13 + 1 + m) * 16;
        f2off[k] = (j < 640 && yok && (unsigned)x2 < 80u)
                   ? (c * 128000 + y2 * 1600 + x2 * 20 + 4 * m) : (int)0x80000000;
    }

    // ---- zeroing: interior blocks only need f2 guard quads; edge blocks all ----
    if (yok) {
        float4 z4 = make_float4(0.f, 0.f, 0.f, 0.f);
        if (x2b == 0 || x2b == 5) {
            for (int i = tid; i < 5248; i += 240) ((float4*)smem)[i] = z4;
        } else {
            // 512 guard quads: 2 buffers x 8 c x 16 x2l x {quad 0, quad 6}
            for (int i = tid; i < 512; i += 240) {
                int e   = i & 255;
                int cx  = e >> 1;                  // c*16 + x2l  (0..127)
                int g   = (e & 1) * 6;
                int quad = F2BASEQ + (i >> 8) * (F2B / 16) + cx * 13 + g;
                ((float4*)smem)[quad] = z4;
            }
        }
    }
    __syncthreads();

    // ---- prologue: issue phase 0 into buffer 0 ----
    if (f1off[0] >= 0) cp16(f1dst[0], f1 + f1off[0]);
    if (f1off[1] >= 0) cp16(f1dst[1], f1 + f1off[1]);
    if (f1off[2] >= 0) cp16(f1dst[2], f1 + f1off[2]);
    if (f1off[3] >= 0) cp16(f1dst[3], f1 + f1off[3]);
    if (f2off[0] >= 0) cp16(f2dst[0], f2 + f2off[0]);
    if (f2off[1] >= 0) cp16(f2dst[1], f2 + f2off[1]);
    if (f2off[2] >= 0) cp16(f2dst[2], f2 + f2off[2]);
    cp_commit();

    ull acc[30];
    #pragma unroll
    for (int i = 0; i < 30; ++i) acc[i] = 0ull;

    const int aq0 = (x2c + 8 - djg * 3) * 5 + zq;   // f1 quad idx (jl subtracts 5)
    const int bq0 = x2c * 13 + zq;                  // f2 quad idx within channel

    #pragma unroll 2
    for (int p = 0; p < 4; ++p) {
        const int cur = p & 1;
        cp_wait<0>();          // phase-p data has arrived
        __syncthreads();       // visible to all; all finished compute(p-1) on buf[1-cur]
        // issue phase p+1 into buf[1-cur] (safe: barrier above) — overlaps compute(p)
        if (p < 3) {
            const int adv = (p + 1) * CADV;
            const unsigned b1 = (1 - cur) * F1B, b2 = (1 - cur) * F2B;
            if (f1off[0] >= 0) cp16(f1dst[0] + b1, f1 + f1off[0] + adv);
            if (f1off[1] >= 0) cp16(f1dst[1] + b1, f1 + f1off[1] + adv);
            if (f1off[2] >= 0) cp16(f1dst[2] + b1, f1 + f1off[2] + adv);
            if (f1off[3] >= 0) cp16(f1dst[3] + b1, f1 + f1off[3] + adv);
            if (f2off[0] >= 0) cp16(f2dst[0] + b2, f2 + f2off[0] + adv);
            if (f2off[1] >= 0) cp16(f2dst[1] + b2, f2 + f2off[1] + adv);
            if (f2off[2] >= 0) cp16(f2dst[2] + b2, f2 + f2off[2] + adv);
            cp_commit();
        }

        if (yok) {
            const float* f1b = smem + cur * (F1B / 4);
            const float* f2b = smem + (F2BASE + cur * F2B) / 4;
            // operand pipeline: B ping-pong (distance 1 ch), A 3-slot JIT rotation
            BW B0, B1;
            ulonglong2 A0, A1, A2;
            loadB(B0, f2b, 0, bq0);
            A0 = loadA(f1b, 0, aq0);
            A1 = loadA(f1b, 0, aq0 - 5);
            A2 = loadA(f1b, 0, aq0 - 10);
            loadB(B1, f2b, 1, bq0);
            #pragma unroll
            for (int cl = 0; cl < 8; ++cl) {
                const BW& Bc = (cl & 1) ? B1 : B0;
                ull P1 = shiftpair(Bc.q0hi, Bc.Q1.x);
                ull P3 = shiftpair(Bc.Q1.x, Bc.Q1.y);
                ull P5 = shiftpair(Bc.Q1.y, Bc.q2lo);
                fma10(acc +  0, A0, Bc, P1, P3, P5);
                if (cl < 7) A0 = loadA(f1b, cl + 1, aq0);
                fma10(acc + 10, A1, Bc, P1, P3, P5);
                if (cl < 7) A1 = loadA(f1b, cl + 1, aq0 - 5);
                fma10(acc + 20, A2, Bc, P1, P3, P5);
                if (cl < 7) A2 = loadA(f1b, cl + 1, aq0 - 10);
                // refill the slot just consumed with channel cl+2
                if (cl < 6) loadB((cl & 1) ? B1 : B0, f2b, cl + 2, bq0);
            }
        }
    }

    // ---- epilogue: coalesced stores (z-fastest across lanes) ----
    // note: !spin => m2v = 1 => mIn == m1, so mask element = inrange ? mIn : m1
    {
        const bool x2ok = ((unsigned)x2g < 80u);
        const bool spin = yok && x2ok;
        const float m2v = spin ? g_mask2[y2 * 80 + x2g] : 1.f;
        const float inv = 1.f / 32.f;
        #pragma unroll
        for (int jl = 0; jl < 3; ++jl) {
            const int dj = djg * 3 + jl;
            const int x  = x2g + 4 - dj;
            if ((unsigned)x < 80u) {
                const float m1  = g_mask1[y * 80 + x];
                const float mIn = m1 * m2v;
                float* pc = out + (size_t)(di * 9 + dj) * 128000
                                + y * 1600 + x * 20 + 4 * zq;
                float* pm = pc + NTOT;
                #pragma unroll
                for (int dk = 0; dk < 5; ++dk) {
                    float4 cv;
                    unpack2(acc[jl * 10 + dk * 2 + 0], cv.x, cv.y);
                    unpack2(acc[jl * 10 + dk * 2 + 1], cv.z, cv.w);
                    cv.x *= inv; cv.y *= inv; cv.z *= inv; cv.w *= inv;
                    *(float4*)pc = cv;
                    float4 mv;
                    {
                        float* mp = (float*)&mv;
                        #pragma unroll
                        for (int zl = 0; zl < 4; ++zl) {
                            int z2 = 4 * zq + zl + dk - 2;
                            mp[zl] = ((unsigned)z2 < 20u) ? mIn : m1;
                        }
                    }
                    *(float4*)pm = mv;
                    pc += (size_t)81 * 128000;
                    pm += (size_t)81 * 128000;
                }
            }
        }
    }
}

extern "C" void kernel_launch(void* const* d_in, const int* in_sizes, int n_in,
                              void* d_out, int out_size)
{
    (void)in_sizes; (void)n_in; (void)out_size;
    const float* f1 = (const float*)d_in[0];
    const float* a1 = (const float*)d_in[1];
    const float* f2 = (const float*)d_in[2];
    const float* a2 = (const float*)d_in[3];
    float* out = (float*)d_out;

    cudaFuncSetAttribute(corr_kernel, cudaFuncAttributeMaxDynamicSharedMemorySize, 83968);

    mask_prep<<<25, 256>>>(a1, a2);
    corr_kernel<<<dim3(6, 80, 9), 240, 83968>>>(f1, f2, out);
}